// round 1
// baseline (speedup 1.0000x reference)
#include <cuda_runtime.h>
#include <math_constants.h>

#define B_ROWS   4096
#define N_COL    16384
#define M_BINS   100
#define H_BINS   101      // histogram slots 0..100 (slot 0 and 100 are edge/tail)
#define NTHREADS 256
#define NWARPS   (NTHREADS / 32)
#define HPAD     104      // replica stride (pads banks a bit)

__global__ __launch_bounds__(NTHREADS)
void roc_model_kernel(const float* __restrict__ x,
                      const float* __restrict__ y,
                      float* __restrict__ out)
{
    __shared__ float hist[NWARPS][HPAD];   // per-warp histogram replicas
    __shared__ float ts[H_BINS + 1];       // exact t table, ts[100] = +inf sentinel
    __shared__ float fh[H_BINS];           // reduced histogram
    __shared__ float sfx[M_BINS];          // suffix sums of "full"

    const int row = blockIdx.x;
    const int tid = threadIdx.x;
    const int wid = tid >> 5;

    // init replicas
    float* hflat = &hist[0][0];
    #pragma unroll
    for (int i = tid; i < NWARPS * HPAD; i += NTHREADS) hflat[i] = 0.0f;

    // Exact linspace(0,1,100) as JAX computes it: t[i] = fl(i / 99) (true division).
    if (tid < 100) ts[tid] = __fdiv_rn((float)tid, 99.0f);
    if (tid == 0)  ts[100] = CUDART_INF_F;
    __syncthreads();

    // ---- Phase 1: value-sum histogram of this row ----
    const float4* xr = reinterpret_cast<const float4*>(x + (size_t)row * N_COL);
    float* h = hist[wid];

    #pragma unroll 4
    for (int it = 0; it < N_COL / 4 / NTHREADS; ++it) {
        float4 v = xr[tid + it * NTHREADS];
        float vv[4] = {v.x, v.y, v.z, v.w};
        #pragma unroll
        for (int c = 0; c < 4; ++c) {
            float xv = vv[c];
            // guess bin, then correct against the exact table.
            int i = (int)(xv * 99.0f);
            if (i < 0) i = 0;
            if (i > 99) i = 99;
            // searchsorted 'left': smallest i with t[i] >= x  (i == b+1)
            while (ts[i] < xv) ++i;                 // ts[100]=inf terminates
            while (i > 0 && ts[i - 1] >= xv) --i;
            atomicAdd(&h[i], xv);
        }
    }
    __syncthreads();

    // ---- Phase 2: reduce replicas ----
    if (tid < H_BINS) {
        float s = 0.0f;
        #pragma unroll
        for (int w = 0; w < NWARPS; ++w) s += hist[w][tid];
        fh[tid] = s;
    }
    __syncthreads();

    // ---- Phase 3: suffix sums (serial on thread 0, matches flip-cumsum-flip order) ----
    if (tid == 0) {
        float acc = 0.0f;
        #pragma unroll
        for (int k = M_BINS - 1; k >= 0; --k) {
            // full[k] = fh[k+1] for k<99 ; full[99] = fh[100]
            float f = (k == M_BINS - 1) ? fh[100] : fh[k + 1];
            acc += f;
            sfx[k] = acc;
        }
    }
    __syncthreads();

    const float invy = 1.0f / y[row];

    // ---- Phase 4: write curves ----
    if (tid < M_BINS) {
        float roc = sfx[tid] * invy;
        out[(size_t)row * M_BINS + tid] = roc;

        float d;
        if (tid < M_BINS - 1) d = fh[tid + 1] * invy;                    // bins[k]
        else                  d = (fh[99] + fh[98]) * 0.5f * invy;       // deriv_last
        out[(size_t)B_ROWS * M_BINS + (size_t)row * M_BINS + tid] = d;
    }

    // ---- Phase 5: trapz scalars (thread 0) ----
    if (tid == 0) {
        float t1 = 0.0f, t2 = 0.0f;
        float prev_r = sfx[0] * invy;
        float prev_d = fh[1] * invy;
        #pragma unroll
        for (int k = 1; k < M_BINS; ++k) {
            float r = sfx[k] * invy;
            float d = (k < M_BINS - 1) ? fh[k + 1] * invy
                                       : (fh[99] + fh[98]) * 0.5f * invy;
            t1 += (prev_r + r) * 0.5f;
            t2 += (prev_d + d) * 0.5f;
            prev_r = r; prev_d = d;
        }
        out[(size_t)B_ROWS * M_BINS * 2 + row]          = t1;
        out[(size_t)B_ROWS * M_BINS * 2 + B_ROWS + row] = t2;
    }
}

extern "C" void kernel_launch(void* const* d_in, const int* in_sizes, int n_in,
                              void* d_out, int out_size)
{
    const float* x = (const float*)d_in[0];   // [4096, 16384] fp32
    const float* y = (const float*)d_in[1];   // [4096] fp32
    float* out = (float*)d_out;

    roc_model_kernel<<<B_ROWS, NTHREADS>>>(x, y, out);
}